// round 1
// baseline (speedup 1.0000x reference)
#include <cuda_runtime.h>
#include <math.h>

// Problem constants
#define NB    8
#define NH    4
#define NSEQ  2048
#define FIN   256
#define DHEAD 64
#define ALPHA 0.2f

// Flash tile config
#define BM  128   // Q rows per block
#define BKV 64    // KV rows per tile
#define QTP 132   // padded row length for [d][row] layouts (BM + pad)
#define KTP 68    // padded row length for [d][kv] / [kv][d] layouts

// Scratch: per-head projections P[b,h,n,d]  (16 MB, device global => no alloc)
__device__ float g_P[(size_t)NB * NH * NSEQ * DHEAD];

// ---------------------------------------------------------------------------
// Kernel 1: projection  P[b,h,n,d] = sum_f h[b,n,f] * W[h,f,d]
// Viewed as GEMM: A [16384 x 256] (h flattened) times W[head] [256 x 64].
// Block = 64 rows x 64 cols (one head), 128 threads, microtile 8x4.
// ---------------------------------------------------------------------------
__global__ __launch_bounds__(128) void proj_kernel(const float* __restrict__ hin,
                                                   const float* __restrict__ W)
{
    __shared__ float Ast[16][68];   // A tile transposed: [k][row]
    __shared__ float Bs [16][68];   // W tile:            [k][d]

    const int tid = threadIdx.x;
    const int ct  = blockIdx.x;          // head index (col tile, BN==D==64)
    const int rt  = blockIdx.y;          // row tile over 16384 rows
    const int tx  = tid & 15;            // col group (4 cols)
    const int ty  = tid >> 4;            // row group (8 rows), 0..7

    const float* Atile = hin + (size_t)rt * 64 * FIN;
    const float* Btile = W   + (size_t)ct * FIN * DHEAD;

    float acc[8][4];
#pragma unroll
    for (int i = 0; i < 8; i++)
#pragma unroll
        for (int j = 0; j < 4; j++) acc[i][j] = 0.f;

    for (int k0 = 0; k0 < FIN; k0 += 16) {
        // Load A tile (64 rows x 16 k), store transposed
#pragma unroll
        for (int i = 0; i < 2; i++) {
            int f4  = i * 128 + tid;          // 0..255 (4 float4 per row)
            int row = f4 >> 2;
            int kk  = (f4 & 3) * 4;
            float4 v = *(const float4*)(Atile + (size_t)row * FIN + k0 + kk);
            Ast[kk + 0][row] = v.x;
            Ast[kk + 1][row] = v.y;
            Ast[kk + 2][row] = v.z;
            Ast[kk + 3][row] = v.w;
        }
        // Load W tile (16 k x 64 d), row-major
#pragma unroll
        for (int i = 0; i < 2; i++) {
            int f4 = i * 128 + tid;           // 0..255 (16 float4 per k-row)
            int kk = f4 >> 4;
            int dd = (f4 & 15) * 4;
            float4 v = *(const float4*)(Btile + (size_t)(k0 + kk) * DHEAD + dd);
            *(float4*)&Bs[kk][dd] = v;
        }
        __syncthreads();

#pragma unroll
        for (int k = 0; k < 16; k++) {
            float4 a0 = *(float4*)&Ast[k][ty * 8];
            float4 a1 = *(float4*)&Ast[k][ty * 8 + 4];
            float4 bv = *(float4*)&Bs[k][tx * 4];
            float a[8] = {a0.x, a0.y, a0.z, a0.w, a1.x, a1.y, a1.z, a1.w};
            float b[4] = {bv.x, bv.y, bv.z, bv.w};
#pragma unroll
            for (int i = 0; i < 8; i++)
#pragma unroll
                for (int j = 0; j < 4; j++)
                    acc[i][j] = fmaf(a[i], b[j], acc[i][j]);
        }
        __syncthreads();
    }

    // Epilogue: write P[b, head=ct, n, d]
#pragma unroll
    for (int i = 0; i < 8; i++) {
        int grow = rt * 64 + ty * 8 + i;       // global row over b*N+n
        int b = grow >> 11;                    // / 2048
        int n = grow & 2047;
        float* dst = g_P + (((size_t)(b * NH + ct) * NSEQ + n) * DHEAD) + tx * 4;
        *(float4*)dst = make_float4(acc[i][0], acc[i][1], acc[i][2], acc[i][3]);
    }
}

// ---------------------------------------------------------------------------
// Kernel 2: fused flash attention over P, per (b,h):
//   O = softmax(leakyrelu(P P^T)) P ; out = concat_heads(O) + h
// Block: 128 Q rows, loop over 32 KV tiles of 64. 256 threads,
// thread grid 16(row groups of 8) x 16(col groups of 4).
// ---------------------------------------------------------------------------
extern __shared__ float smem[];

__global__ void flash_kernel(const float* __restrict__ hin,
                             float* __restrict__ out)
{
    float* Qt = smem;                 // [64][QTP]  Q transposed: [d][row]
    float* Kt = Qt + 64 * QTP;        // [64][KTP]  K transposed: [d][kv]
    float* Ks = Kt + 64 * KTP;        // [64][KTP]  K row-major:  [kv][d]
    float* Pt = Ks + 64 * KTP;        // [64][QTP]  expP transposed: [kv][row]

    const int tid = threadIdx.x;
    const int tx  = tid & 15;         // col group (4)
    const int ty  = tid >> 4;         // row group (8), 0..15
    const int bh  = blockIdx.y;       // b*NH + h
    const int qb  = blockIdx.x * BM;

    const float* Pg = g_P + (size_t)bh * NSEQ * DHEAD;

    // Load Q tile transposed: 128 rows x 64 d = 2048 float4
#pragma unroll
    for (int i = 0; i < 8; i++) {
        int f4  = i * 256 + tid;
        int row = f4 >> 4;            // 16 float4 per row
        int dd  = (f4 & 15) * 4;
        float4 v = *(const float4*)(Pg + (size_t)(qb + row) * DHEAD + dd);
        Qt[(dd + 0) * QTP + row] = v.x;
        Qt[(dd + 1) * QTP + row] = v.y;
        Qt[(dd + 2) * QTP + row] = v.z;
        Qt[(dd + 3) * QTP + row] = v.w;
    }

    float m[8], l[8], o[8][4];
#pragma unroll
    for (int i = 0; i < 8; i++) {
        m[i] = -INFINITY;
        l[i] = 0.f;
#pragma unroll
        for (int j = 0; j < 4; j++) o[i][j] = 0.f;
    }

    for (int kt = 0; kt < NSEQ / BKV; kt++) {
        __syncthreads();   // protect Ks/Kt/Pt reuse across iterations (+Qt on iter 0 via next sync)

        // Load K tile (64 x 64): both row-major (Ks) and transposed (Kt)
#pragma unroll
        for (int i = 0; i < 4; i++) {
            int f4  = i * 256 + tid;
            int row = f4 >> 4;
            int dd  = (f4 & 15) * 4;
            float4 v = *(const float4*)(Pg + (size_t)(kt * BKV + row) * DHEAD + dd);
            *(float4*)&Ks[row * KTP + dd] = v;
            Kt[(dd + 0) * KTP + row] = v.x;
            Kt[(dd + 1) * KTP + row] = v.y;
            Kt[(dd + 2) * KTP + row] = v.z;
            Kt[(dd + 3) * KTP + row] = v.w;
        }
        __syncthreads();

        // GEMM1: S = Q K^T  (per-thread 8x4 microtile)
        float s[8][4];
#pragma unroll
        for (int i = 0; i < 8; i++)
#pragma unroll
            for (int j = 0; j < 4; j++) s[i][j] = 0.f;

#pragma unroll 4
        for (int d = 0; d < DHEAD; d++) {
            float4 q0 = *(float4*)&Qt[d * QTP + ty * 8];
            float4 q1 = *(float4*)&Qt[d * QTP + ty * 8 + 4];
            float4 kv = *(float4*)&Kt[d * KTP + tx * 4];
            float q[8] = {q0.x, q0.y, q0.z, q0.w, q1.x, q1.y, q1.z, q1.w};
            float k[4] = {kv.x, kv.y, kv.z, kv.w};
#pragma unroll
            for (int i = 0; i < 8; i++)
#pragma unroll
                for (int j = 0; j < 4; j++)
                    s[i][j] = fmaf(q[i], k[j], s[i][j]);
        }

        // LeakyReLU + online softmax update (row state replicated over 16 col-threads)
#pragma unroll
        for (int i = 0; i < 8; i++) {
            float rm = -INFINITY;
#pragma unroll
            for (int j = 0; j < 4; j++) {
                float v = s[i][j];
                v = (v > 0.f) ? v : ALPHA * v;
                s[i][j] = v;
                rm = fmaxf(rm, v);
            }
#pragma unroll
            for (int off = 8; off >= 1; off >>= 1)
                rm = fmaxf(rm, __shfl_xor_sync(0xffffffffu, rm, off));

            float mnew = fmaxf(m[i], rm);
            float corr = __expf(m[i] - mnew);
            float rs = 0.f;
#pragma unroll
            for (int j = 0; j < 4; j++) {
                float p = __expf(s[i][j] - mnew);
                s[i][j] = p;
                rs += p;
            }
#pragma unroll
            for (int off = 8; off >= 1; off >>= 1)
                rs += __shfl_xor_sync(0xffffffffu, rs, off);

            l[i] = l[i] * corr + rs;
            m[i] = mnew;
#pragma unroll
            for (int j = 0; j < 4; j++) o[i][j] *= corr;
        }

        // Store expP transposed: Pt[kv][row]
#pragma unroll
        for (int j = 0; j < 4; j++) {
            int c = tx * 4 + j;
            *(float4*)&Pt[c * QTP + ty * 8] =
                make_float4(s[0][j], s[1][j], s[2][j], s[3][j]);
            *(float4*)&Pt[c * QTP + ty * 8 + 4] =
                make_float4(s[4][j], s[5][j], s[6][j], s[7][j]);
        }
        __syncthreads();

        // GEMM2: O += expP @ V   (V tile == K tile, row-major Ks)
#pragma unroll 4
        for (int c = 0; c < BKV; c++) {
            float4 p0 = *(float4*)&Pt[c * QTP + ty * 8];
            float4 p1 = *(float4*)&Pt[c * QTP + ty * 8 + 4];
            float4 kv = *(float4*)&Ks[c * KTP + tx * 4];
            float p[8] = {p0.x, p0.y, p0.z, p0.w, p1.x, p1.y, p1.z, p1.w};
            float v[4] = {kv.x, kv.y, kv.z, kv.w};
#pragma unroll
            for (int i = 0; i < 8; i++)
#pragma unroll
                for (int j = 0; j < 4; j++)
                    o[i][j] = fmaf(p[i], v[j], o[i][j]);
        }
    }

    // Epilogue: normalize, concat heads, add residual h
    const int hh = bh & (NH - 1);
    const int b  = bh >> 2;
#pragma unroll
    for (int i = 0; i < 8; i++) {
        float inv = 1.0f / l[i];
        int n = qb + ty * 8 + i;
        size_t off = ((size_t)(b * NSEQ + n)) * FIN + hh * DHEAD + tx * 4;
        float4 hv = *(const float4*)(hin + off);
        float4 r;
        r.x = fmaf(o[i][0], inv, hv.x);
        r.y = fmaf(o[i][1], inv, hv.y);
        r.z = fmaf(o[i][2], inv, hv.z);
        r.w = fmaf(o[i][3], inv, hv.w);
        *(float4*)(out + off) = r;
    }
}

// ---------------------------------------------------------------------------
extern "C" void kernel_launch(void* const* d_in, const int* in_sizes, int n_in,
                              void* d_out, int out_size)
{
    const float* h = (const float*)d_in[0];
    // d_in[1] = adj : unused by the reference computation
    const float* W = (const float*)d_in[2];
    float* out = (float*)d_out;

    // Projection: grid (heads=4, row tiles=256)
    proj_kernel<<<dim3(NH, (NB * NSEQ) / 64), 128>>>(h, W);

    // Fused flash attention + residual
    const int smem_bytes = (64 * QTP * 2 + 64 * KTP * 2) * (int)sizeof(float); // 102400
    cudaFuncSetAttribute(flash_kernel, cudaFuncAttributeMaxDynamicSharedMemorySize,
                         smem_bytes);
    flash_kernel<<<dim3(NSEQ / BM, NB * NH), 256, smem_bytes>>>(h, out);
}

// round 3
// speedup vs baseline: 1.1229x; 1.1229x over previous
#include <cuda_runtime.h>
#include <math.h>

// Problem constants
#define NB    8
#define NH    4
#define NSEQ  2048
#define FIN   256
#define DHEAD 64
#define ALPHA 0.2f

// Flash tile config
#define BM  128   // Q rows per block
#define BKV 64    // KV rows per tile
#define QTP 132   // padded row length for [d][row] layouts (BM + pad)
#define KTP 68    // padded row length for [d][kv] / [kv][d] layouts

typedef unsigned long long u64;

// ---- packed f32x2 helpers (Blackwell FFMA2: only reachable via PTX) --------
__device__ __forceinline__ u64 bc2(float x) {           // pack {x, x}
    u64 r;
    asm("mov.b64 %0, {%1, %1};" : "=l"(r) : "r"(__float_as_uint(x)));
    return r;
}
__device__ __forceinline__ u64 pk2(float lo, float hi) { // pack {lo, hi}
    u64 r;
    asm("mov.b64 %0, {%1, %2};" : "=l"(r) : "r"(__float_as_uint(lo)), "r"(__float_as_uint(hi)));
    return r;
}
__device__ __forceinline__ void up2(u64 v, float& lo, float& hi) {
    unsigned int a, b;
    asm("mov.b64 {%0, %1}, %2;" : "=r"(a), "=r"(b) : "l"(v));
    lo = __uint_as_float(a);
    hi = __uint_as_float(b);
}
__device__ __forceinline__ void fma2(u64& d, u64 a, u64 b) {
    asm("fma.rn.f32x2 %0, %1, %2, %0;" : "+l"(d) : "l"(a), "l"(b));
}
__device__ __forceinline__ void mul2(u64& d, u64 a) {
    asm("mul.rn.f32x2 %0, %0, %1;" : "+l"(d) : "l"(a));
}

// Scratch: per-head projections P[b,h,n,d]  (16 MB, device global => no alloc)
__device__ float g_P[(size_t)NB * NH * NSEQ * DHEAD];

// ---------------------------------------------------------------------------
// Kernel 1: projection  P[b,h,n,d] = sum_f h[b,n,f] * W[h,f,d]
// Block = 64 rows x 64 cols (one head), 128 threads, microtile 8x4 (row-paired
// FFMA2: 4 row-pairs x 4 cols).
// ---------------------------------------------------------------------------
__global__ __launch_bounds__(128) void proj_kernel(const float* __restrict__ hin,
                                                   const float* __restrict__ W)
{
    __shared__ float Ast[16][68];   // A tile transposed: [k][row]
    __shared__ float Bs [16][68];   // W tile:            [k][d]

    const int tid = threadIdx.x;
    const int ct  = blockIdx.x;          // head index
    const int rt  = blockIdx.y;          // row tile over 16384 rows
    const int tx  = tid & 15;            // col group (4 cols)
    const int ty  = tid >> 4;            // row group (8 rows), 0..7

    const float* Atile = hin + (size_t)rt * 64 * FIN;
    const float* Btile = W   + (size_t)ct * FIN * DHEAD;

    u64 acc2[4][4];
#pragma unroll
    for (int i = 0; i < 4; i++)
#pragma unroll
        for (int j = 0; j < 4; j++) acc2[i][j] = 0ULL;

    for (int k0 = 0; k0 < FIN; k0 += 16) {
#pragma unroll
        for (int i = 0; i < 2; i++) {
            int f4  = i * 128 + tid;
            int row = f4 >> 2;
            int kk  = (f4 & 3) * 4;
            float4 v = *(const float4*)(Atile + (size_t)row * FIN + k0 + kk);
            Ast[kk + 0][row] = v.x;
            Ast[kk + 1][row] = v.y;
            Ast[kk + 2][row] = v.z;
            Ast[kk + 3][row] = v.w;
        }
#pragma unroll
        for (int i = 0; i < 2; i++) {
            int f4 = i * 128 + tid;
            int kk = f4 >> 4;
            int dd = (f4 & 15) * 4;
            float4 v = *(const float4*)(Btile + (size_t)(k0 + kk) * DHEAD + dd);
            *(float4*)&Bs[kk][dd] = v;
        }
        __syncthreads();

#pragma unroll
        for (int k = 0; k < 16; k++) {
            ulonglong2 a0 = *(ulonglong2*)&Ast[k][ty * 8];
            ulonglong2 a1 = *(ulonglong2*)&Ast[k][ty * 8 + 4];
            float4 bv = *(float4*)&Bs[k][tx * 4];
            u64 ap[4] = {a0.x, a0.y, a1.x, a1.y};
            u64 b0 = bc2(bv.x), b1 = bc2(bv.y), b2 = bc2(bv.z), b3 = bc2(bv.w);
#pragma unroll
            for (int i = 0; i < 4; i++) {
                fma2(acc2[i][0], ap[i], b0);
                fma2(acc2[i][1], ap[i], b1);
                fma2(acc2[i][2], ap[i], b2);
                fma2(acc2[i][3], ap[i], b3);
            }
        }
        __syncthreads();
    }

    // Epilogue: unpack and write P[b, head=ct, n, d]
#pragma unroll
    for (int i2 = 0; i2 < 4; i2++) {
        float lo[4], hi[4];
#pragma unroll
        for (int j = 0; j < 4; j++) up2(acc2[i2][j], lo[j], hi[j]);
#pragma unroll
        for (int p = 0; p < 2; p++) {
            int grow = rt * 64 + ty * 8 + i2 * 2 + p;
            int b = grow >> 11;
            int n = grow & 2047;
            float* dst = g_P + (((size_t)(b * NH + ct) * NSEQ + n) * DHEAD) + tx * 4;
            float* src = p ? hi : lo;
            *(float4*)dst = make_float4(src[0], src[1], src[2], src[3]);
        }
    }
}

// ---------------------------------------------------------------------------
// Kernel 2: fused flash attention over P, per (b,h):
//   O = softmax(leakyrelu(P P^T)) P ; out = concat_heads(O) + h
// 256 threads, microtile 8x4 per thread, row-paired FFMA2.
// ---------------------------------------------------------------------------
extern __shared__ float smem[];

__global__ void flash_kernel(const float* __restrict__ hin,
                             float* __restrict__ out)
{
    float* Qt = smem;                 // [64][QTP]  Q transposed: [d][row]
    float* Kt = Qt + 64 * QTP;        // [64][KTP]  K transposed: [d][kv]
    float* Ks = Kt + 64 * KTP;        // [64][KTP]  K row-major:  [kv][d]
    float* Pt = Ks + 64 * KTP;        // [64][QTP]  expP transposed: [kv][row]

    const int tid = threadIdx.x;
    const int tx  = tid & 15;         // col group (4)
    const int ty  = tid >> 4;         // row group (8), 0..15
    const int bh  = blockIdx.y;       // b*NH + h
    const int qb  = blockIdx.x * BM;

    const float* Pg = g_P + (size_t)bh * NSEQ * DHEAD;

    // Load Q tile transposed: 128 rows x 64 d
#pragma unroll
    for (int i = 0; i < 8; i++) {
        int f4  = i * 256 + tid;
        int row = f4 >> 4;
        int dd  = (f4 & 15) * 4;
        float4 v = *(const float4*)(Pg + (size_t)(qb + row) * DHEAD + dd);
        Qt[(dd + 0) * QTP + row] = v.x;
        Qt[(dd + 1) * QTP + row] = v.y;
        Qt[(dd + 2) * QTP + row] = v.z;
        Qt[(dd + 3) * QTP + row] = v.w;
    }

    float m[8], l[8];
    u64 o2[4][4];                     // row-pairs x 4 cols
#pragma unroll
    for (int i = 0; i < 8; i++) { m[i] = -INFINITY; l[i] = 0.f; }
#pragma unroll
    for (int i = 0; i < 4; i++)
#pragma unroll
        for (int j = 0; j < 4; j++) o2[i][j] = 0ULL;

    for (int kt = 0; kt < NSEQ / BKV; kt++) {
        __syncthreads();   // protect Ks/Kt/Pt reuse across iterations

        // Load K tile (64 x 64): both row-major (Ks) and transposed (Kt)
#pragma unroll
        for (int i = 0; i < 4; i++) {
            int f4  = i * 256 + tid;
            int row = f4 >> 4;
            int dd  = (f4 & 15) * 4;
            float4 v = *(const float4*)(Pg + (size_t)(kt * BKV + row) * DHEAD + dd);
            *(float4*)&Ks[row * KTP + dd] = v;
            Kt[(dd + 0) * KTP + row] = v.x;
            Kt[(dd + 1) * KTP + row] = v.y;
            Kt[(dd + 2) * KTP + row] = v.z;
            Kt[(dd + 3) * KTP + row] = v.w;
        }
        __syncthreads();

        // GEMM1: S = Q K^T  (4 row-pairs x 4 cols, FFMA2)
        u64 s2[4][4];
#pragma unroll
        for (int i = 0; i < 4; i++)
#pragma unroll
            for (int j = 0; j < 4; j++) s2[i][j] = 0ULL;

#pragma unroll 4
        for (int d = 0; d < DHEAD; d++) {
            ulonglong2 qa = *(ulonglong2*)&Qt[d * QTP + ty * 8];
            ulonglong2 qb4 = *(ulonglong2*)&Qt[d * QTP + ty * 8 + 4];
            float4 kv = *(float4*)&Kt[d * KTP + tx * 4];
            u64 qp[4] = {qa.x, qa.y, qb4.x, qb4.y};
            u64 k0 = bc2(kv.x), k1 = bc2(kv.y), k2 = bc2(kv.z), k3 = bc2(kv.w);
#pragma unroll
            for (int i = 0; i < 4; i++) {
                fma2(s2[i][0], qp[i], k0);
                fma2(s2[i][1], qp[i], k1);
                fma2(s2[i][2], qp[i], k2);
                fma2(s2[i][3], qp[i], k3);
            }
        }

        // Unpack scores
        float s[8][4];
#pragma unroll
        for (int i2 = 0; i2 < 4; i2++)
#pragma unroll
            for (int j = 0; j < 4; j++)
                up2(s2[i2][j], s[2 * i2][j], s[2 * i2 + 1][j]);

        // LeakyReLU + online softmax update
        float corr[8];
#pragma unroll
        for (int i = 0; i < 8; i++) {
            float rm = -INFINITY;
#pragma unroll
            for (int j = 0; j < 4; j++) {
                float v = s[i][j];
                v = (v > 0.f) ? v : ALPHA * v;
                s[i][j] = v;
                rm = fmaxf(rm, v);
            }
#pragma unroll
            for (int off = 8; off >= 1; off >>= 1)
                rm = fmaxf(rm, __shfl_xor_sync(0xffffffffu, rm, off));

            float mnew = fmaxf(m[i], rm);
            corr[i] = __expf(m[i] - mnew);
            float rs = 0.f;
#pragma unroll
            for (int j = 0; j < 4; j++) {
                float p = __expf(s[i][j] - mnew);
                s[i][j] = p;
                rs += p;
            }
#pragma unroll
            for (int off = 8; off >= 1; off >>= 1)
                rs += __shfl_xor_sync(0xffffffffu, rs, off);

            l[i] = l[i] * corr[i] + rs;
            m[i] = mnew;
        }

        // Rescale O accumulators (packed per row-pair)
#pragma unroll
        for (int i2 = 0; i2 < 4; i2++) {
            u64 c2 = pk2(corr[2 * i2], corr[2 * i2 + 1]);
#pragma unroll
            for (int j = 0; j < 4; j++) mul2(o2[i2][j], c2);
        }

        // Store expP transposed: Pt[kv][row]
#pragma unroll
        for (int j = 0; j < 4; j++) {
            int c = tx * 4 + j;
            *(float4*)&Pt[c * QTP + ty * 8] =
                make_float4(s[0][j], s[1][j], s[2][j], s[3][j]);
            *(float4*)&Pt[c * QTP + ty * 8 + 4] =
                make_float4(s[4][j], s[5][j], s[6][j], s[7][j]);
        }
        __syncthreads();

        // GEMM2: O += expP @ V   (V tile == K tile, row-major Ks)
#pragma unroll 4
        for (int c = 0; c < BKV; c++) {
            ulonglong2 pa = *(ulonglong2*)&Pt[c * QTP + ty * 8];
            ulonglong2 pb = *(ulonglong2*)&Pt[c * QTP + ty * 8 + 4];
            float4 vv = *(float4*)&Ks[c * KTP + tx * 4];
            u64 pp[4] = {pa.x, pa.y, pb.x, pb.y};
            u64 v0 = bc2(vv.x), v1 = bc2(vv.y), v2 = bc2(vv.z), v3 = bc2(vv.w);
#pragma unroll
            for (int i = 0; i < 4; i++) {
                fma2(o2[i][0], pp[i], v0);
                fma2(o2[i][1], pp[i], v1);
                fma2(o2[i][2], pp[i], v2);
                fma2(o2[i][3], pp[i], v3);
            }
        }
    }

    // Epilogue: normalize, concat heads, add residual h
    const int hh = bh & (NH - 1);
    const int b  = bh >> 2;
    float o[8][4];
#pragma unroll
    for (int i2 = 0; i2 < 4; i2++)
#pragma unroll
        for (int j = 0; j < 4; j++)
            up2(o2[i2][j], o[2 * i2][j], o[2 * i2 + 1][j]);

#pragma unroll
    for (int i = 0; i < 8; i++) {
        float inv = 1.0f / l[i];
        int n = qb + ty * 8 + i;
        size_t off = ((size_t)(b * NSEQ + n)) * FIN + hh * DHEAD + tx * 4;
        float4 hv = *(const float4*)(hin + off);
        float4 r;
        r.x = fmaf(o[i][0], inv, hv.x);
        r.y = fmaf(o[i][1], inv, hv.y);
        r.z = fmaf(o[i][2], inv, hv.z);
        r.w = fmaf(o[i][3], inv, hv.w);
        *(float4*)(out + off) = r;
    }
}

// ---------------------------------------------------------------------------
extern "C" void kernel_launch(void* const* d_in, const int* in_sizes, int n_in,
                              void* d_out, int out_size)
{
    const float* h = (const float*)d_in[0];
    // d_in[1] = adj : unused by the reference computation
    const float* W = (const float*)d_in[2];
    float* out = (float*)d_out;

    proj_kernel<<<dim3(NH, (NB * NSEQ) / 64), 128>>>(h, W);

    const int smem_bytes = (64 * QTP * 2 + 64 * KTP * 2) * (int)sizeof(float); // 102400
    cudaFuncSetAttribute(flash_kernel, cudaFuncAttributeMaxDynamicSharedMemorySize,
                         smem_bytes);
    flash_kernel<<<dim3(NSEQ / BM, NB * NH), 256, smem_bytes>>>(h, out);
}

// round 6
// speedup vs baseline: 2.6965x; 2.4013x over previous
#include <cuda_runtime.h>
#include <cuda_bf16.h>
#include <math.h>
#include <stdint.h>

// Problem constants
#define NB    8
#define NH    4
#define NSEQ  2048
#define FIN   256
#define DHEAD 64
#define ALPHA 0.2f
#define BHTOT (NB*NH)

// Flash tiles
#define QM     128
#define KV     128
#define NTILES (NSEQ/KV)

typedef unsigned long long u64;
typedef unsigned int u32;
typedef unsigned long long ull;

// ===========================================================================
// Helpers
// ===========================================================================
__device__ __forceinline__ u32 smem_u32(const void* p) {
    u32 a;
    asm("{ .reg .u64 t; cvta.to.shared.u64 t, %1; cvt.u32.u64 %0, t; }" : "=r"(a) : "l"(p));
    return a;
}
__device__ __forceinline__ void ldsm_x4(u32 addr, u32& r0, u32& r1, u32& r2, u32& r3) {
    asm volatile("ldmatrix.sync.aligned.m8n8.x4.shared.b16 {%0,%1,%2,%3}, [%4];"
                 : "=r"(r0), "=r"(r1), "=r"(r2), "=r"(r3) : "r"(addr));
}
__device__ __forceinline__ void ldsm_x4_t(u32 addr, u32& r0, u32& r1, u32& r2, u32& r3) {
    asm volatile("ldmatrix.sync.aligned.m8n8.x4.trans.shared.b16 {%0,%1,%2,%3}, [%4];"
                 : "=r"(r0), "=r"(r1), "=r"(r2), "=r"(r3) : "r"(addr));
}
__device__ __forceinline__ void mma16816(float* c, const u32* a, u32 b0, u32 b1) {
    asm volatile("mma.sync.aligned.m16n8k16.row.col.f32.bf16.bf16.f32 "
                 "{%0,%1,%2,%3}, {%4,%5,%6,%7}, {%8,%9}, {%0,%1,%2,%3};"
                 : "+f"(c[0]), "+f"(c[1]), "+f"(c[2]), "+f"(c[3])
                 : "r"(a[0]), "r"(a[1]), "r"(a[2]), "r"(a[3]), "r"(b0), "r"(b1));
}
__device__ __forceinline__ u32 packbf(float lo, float hi) {
    __nv_bfloat162 t = __floats2bfloat162_rn(lo, hi);   // .x = lo (low half)
    return *(u32*)&t;
}
__device__ __forceinline__ float2 unpackbf(u32 v) {
    return __bfloat1622float2(*(__nv_bfloat162*)&v);
}

// f32x2 packed FMA helpers (projection kernel)
__device__ __forceinline__ ull bc2(float x) {
    ull r; asm("mov.b64 %0, {%1, %1};" : "=l"(r) : "r"(__float_as_uint(x))); return r;
}
__device__ __forceinline__ void up2(ull v, float& lo, float& hi) {
    u32 a, b; asm("mov.b64 {%0, %1}, %2;" : "=r"(a), "=r"(b) : "l"(v));
    lo = __uint_as_float(a); hi = __uint_as_float(b);
}
__device__ __forceinline__ void fma2(ull& d, ull a, ull b) {
    asm("fma.rn.f32x2 %0, %1, %2, %0;" : "+l"(d) : "l"(a), "l"(b));
}

// ===========================================================================
// Global scratch (no allocs allowed)
// ===========================================================================
__device__ __nv_bfloat16 g_Ph[(size_t)BHTOT * NSEQ * DHEAD];
__device__ __nv_bfloat16 g_Pl[(size_t)BHTOT * NSEQ * DHEAD];
__device__ float g_norm2[(size_t)BHTOT * NSEQ];
__device__ float g_kmax2[BHTOT];

// ===========================================================================
// Kernel 1: projection P = h @ W  -> bf16 split (hi, lo)
// ===========================================================================
__global__ __launch_bounds__(128) void proj_kernel(const float* __restrict__ hin,
                                                   const float* __restrict__ W)
{
    __shared__ float Ast[16][68];
    __shared__ float Bs [16][68];

    const int tid = threadIdx.x;
    const int ct  = blockIdx.x;
    const int rt  = blockIdx.y;
    const int tx  = tid & 15;
    const int ty  = tid >> 4;

    const float* Atile = hin + (size_t)rt * 64 * FIN;
    const float* Btile = W   + (size_t)ct * FIN * DHEAD;

    ull acc2[4][4];
#pragma unroll
    for (int i = 0; i < 4; i++)
#pragma unroll
        for (int j = 0; j < 4; j++) acc2[i][j] = 0ULL;

    for (int k0 = 0; k0 < FIN; k0 += 16) {
#pragma unroll
        for (int i = 0; i < 2; i++) {
            int f4 = i * 128 + tid;
            int row = f4 >> 2, kk = (f4 & 3) * 4;
            float4 v = *(const float4*)(Atile + (size_t)row * FIN + k0 + kk);
            Ast[kk + 0][row] = v.x; Ast[kk + 1][row] = v.y;
            Ast[kk + 2][row] = v.z; Ast[kk + 3][row] = v.w;
        }
#pragma unroll
        for (int i = 0; i < 2; i++) {
            int f4 = i * 128 + tid;
            int kk = f4 >> 4, dd = (f4 & 15) * 4;
            *(float4*)&Bs[kk][dd] = *(const float4*)(Btile + (size_t)(k0 + kk) * DHEAD + dd);
        }
        __syncthreads();
#pragma unroll
        for (int k = 0; k < 16; k++) {
            ulonglong2 a0 = *(ulonglong2*)&Ast[k][ty * 8];
            ulonglong2 a1 = *(ulonglong2*)&Ast[k][ty * 8 + 4];
            float4 bv = *(float4*)&Bs[k][tx * 4];
            ull ap[4] = {a0.x, a0.y, a1.x, a1.y};
            ull b0 = bc2(bv.x), b1 = bc2(bv.y), b2 = bc2(bv.z), b3 = bc2(bv.w);
#pragma unroll
            for (int i = 0; i < 4; i++) {
                fma2(acc2[i][0], ap[i], b0); fma2(acc2[i][1], ap[i], b1);
                fma2(acc2[i][2], ap[i], b2); fma2(acc2[i][3], ap[i], b3);
            }
        }
        __syncthreads();
    }

#pragma unroll
    for (int i2 = 0; i2 < 4; i2++) {
        float lo[4], hi[4];
#pragma unroll
        for (int j = 0; j < 4; j++) up2(acc2[i2][j], lo[j], hi[j]);
#pragma unroll
        for (int p = 0; p < 2; p++) {
            int grow = rt * 64 + ty * 8 + i2 * 2 + p;
            int b = grow >> 11, n = grow & 2047;
            size_t off = (((size_t)(b * NH + ct) * NSEQ + n) * DHEAD) + tx * 4;
            const float* src = p ? hi : lo;
#pragma unroll
            for (int j = 0; j < 4; j++) {
                float v = src[j];
                __nv_bfloat16 vh = __float2bfloat16(v);
                float vl = v - __bfloat162float(vh);
                g_Ph[off + j] = vh;
                g_Pl[off + j] = __float2bfloat16(vl);
            }
        }
    }
}

// ===========================================================================
// Kernel 2: row norms + per-(b,h) max norm^2
// ===========================================================================
__global__ __launch_bounds__(256) void norm_kernel()
{
    const int bh = blockIdx.x;
    const int tid = threadIdx.x;
    float mx = 0.f;
    for (int r = tid; r < NSEQ; r += 256) {
        const uint4* ph = (const uint4*)(g_Ph + ((size_t)bh * NSEQ + r) * DHEAD);
        const uint4* pl = (const uint4*)(g_Pl + ((size_t)bh * NSEQ + r) * DHEAD);
        float s = 0.f;
#pragma unroll
        for (int g = 0; g < 8; g++) {
            uint4 a = ph[g], b = pl[g];
            const u32 wa[4] = {a.x, a.y, a.z, a.w};
            const u32 wb[4] = {b.x, b.y, b.z, b.w};
#pragma unroll
            for (int q = 0; q < 4; q++) {
                float2 fa = unpackbf(wa[q]);
                float2 fb = unpackbf(wb[q]);
                float v0 = fa.x + fb.x, v1 = fa.y + fb.y;
                s = fmaf(v0, v0, s); s = fmaf(v1, v1, s);
            }
        }
        g_norm2[(size_t)bh * NSEQ + r] = s;
        mx = fmaxf(mx, s);
    }
    __shared__ float red[8];
#pragma unroll
    for (int off = 16; off >= 1; off >>= 1)
        mx = fmaxf(mx, __shfl_xor_sync(0xffffffffu, mx, off));
    if ((tid & 31) == 0) red[tid >> 5] = mx;
    __syncthreads();
    if (tid == 0) {
        float m = red[0];
#pragma unroll
        for (int w = 1; w < 8; w++) m = fmaxf(m, red[w]);
        g_kmax2[bh] = m;
    }
}

// ===========================================================================
// Kernel 3: mma.sync flash attention (no-rescale single pass) + residual
// 8 warps; warp w owns Q rows [w*16, w*16+16). smem: Qh|Ql|Kh|Kl 16KB each.
// ===========================================================================
extern __shared__ char dyn_smem[];

__global__ __launch_bounds__(256, 1) void flash_kernel(const float* __restrict__ hin,
                                                       float* __restrict__ out)
{
    const int tid = threadIdx.x;
    const int l   = tid & 31;
    const int wid = tid >> 5;
    const int wrow = wid * 16;
    const int g   = l >> 2;        // 0..7
    const int qd  = l & 3;
    const int r7  = l & 7;
    const int bh  = blockIdx.y;
    const int qb  = blockIdx.x * QM;

    // Align smem base to 1KB so swizzle math is clean
    const u32 s_raw = smem_u32(dyn_smem);
    const u32 s0 = (s_raw + 1023u) & ~1023u;
    char* base = dyn_smem + (s0 - s_raw);
    char* Qh = base;          char* Ql = base + 16384;
    char* Kh = base + 32768;  char* Kl = base + 49152;
    const u32 uQh = s0, uQl = s0 + 16384, uKh = s0 + 32768, uKl = s0 + 49152;

    const uint4* gPh = (const uint4*)(g_Ph + (size_t)bh * NSEQ * DHEAD);
    const uint4* gPl = (const uint4*)(g_Pl + (size_t)bh * NSEQ * DHEAD);

    // ---- Load Q tile (hi/lo) with swizzle: 128 rows x 128B ----
#pragma unroll
    for (int i = 0; i < 4; i++) {
        int idx = i * 256 + tid;
        int row = idx >> 3, ch = idx & 7;
        u32 dst = (u32)(row * 128 + ((ch ^ (row & 7)) << 4));
        *(uint4*)(Qh + dst) = gPh[(qb + row) * 8 + ch];
        *(uint4*)(Ql + dst) = gPl[(qb + row) * 8 + ch];
    }
    __syncthreads();

    // ---- Load Q A-fragments (resident all tiles): 4 k-steps x 4 regs x 2 ----
    u32 Ah[4][4], Al[4][4];
#pragma unroll
    for (int s = 0; s < 4; s++) {
        u32 row = (u32)(wrow + (l & 15));
        u32 ch  = (u32)((2 * s + (l >> 4)) ^ r7);
        u32 off = row * 128 + (ch << 4);
        ldsm_x4(uQh + off, Ah[s][0], Ah[s][1], Ah[s][2], Ah[s][3]);
        ldsm_x4(uQl + off, Al[s][0], Al[s][1], Al[s][2], Al[s][3]);
    }

    // ---- Per-row softmax shift: M_r = sqrt(|q_r|^2 * max_k |k|^2) ----
    const float km2 = g_kmax2[bh];
    const float Mr0 = sqrtf(g_norm2[(size_t)bh * NSEQ + qb + wrow + g] * km2);
    const float Mr1 = sqrtf(g_norm2[(size_t)bh * NSEQ + qb + wrow + g + 8] * km2);

    float OC[8][4];
#pragma unroll
    for (int j = 0; j < 8; j++)
#pragma unroll
        for (int e = 0; e < 4; e++) OC[j][e] = 0.f;
    float lsum0 = 0.f, lsum1 = 0.f;

    // Precomputed addressing pieces
    const u32 rowB_off = (u32)((8 * (l >> 4) + r7) * 128);   // MMA1 B row part
    const u32 cbB = (u32)((l >> 3) & 1);                     // MMA1 B chunk half
    const u32 rowV_part = (u32)(l & 15);                     // MMA2 V row part

    for (int t = 0; t < NTILES; t++) {
        __syncthreads();   // previous iteration's ldmatrix reads complete

        // ---- Load K tile t (hi/lo) ----
#pragma unroll
        for (int i = 0; i < 4; i++) {
            int idx = i * 256 + tid;
            int row = idx >> 3, ch = idx & 7;
            u32 dst = (u32)(row * 128 + ((ch ^ (row & 7)) << 4));
            *(uint4*)(Kh + dst) = gPh[(t * KV + row) * 8 + ch];
            *(uint4*)(Kl + dst) = gPl[(t * KV + row) * 8 + ch];
        }
        __syncthreads();

        // ---- MMA1: S = Qh*Kh^T + Ql*Kh^T + Qh*Kl^T ----
        float SC[16][4];
#pragma unroll
        for (int j = 0; j < 16; j++)
#pragma unroll
            for (int e = 0; e < 4; e++) SC[j][e] = 0.f;

#pragma unroll
        for (int s = 0; s < 4; s++) {
            u32 chsw = (u32)(((2 * s + cbB) ^ r7) << 4);
#pragma unroll
            for (int jp = 0; jp < 8; jp++) {
                u32 off = (u32)(jp * 16 * 128) + rowB_off + chsw;
                u32 b0, b1, b2, b3;
                ldsm_x4(uKh + off, b0, b1, b2, b3);
                mma16816(SC[2 * jp],     Ah[s], b0, b1);
                mma16816(SC[2 * jp + 1], Ah[s], b2, b3);
                mma16816(SC[2 * jp],     Al[s], b0, b1);
                mma16816(SC[2 * jp + 1], Al[s], b2, b3);
                u32 c0, c1, c2, c3;
                ldsm_x4(uKl + off, c0, c1, c2, c3);
                mma16816(SC[2 * jp],     Ah[s], c0, c1);
                mma16816(SC[2 * jp + 1], Ah[s], c2, c3);
            }
        }

        // ---- LeakyReLU + exp(x - Mr), accumulate row sums ----
#pragma unroll
        for (int j = 0; j < 16; j++) {
#pragma unroll
            for (int e = 0; e < 4; e++) {
                float x = SC[j][e];
                x = fmaxf(x, ALPHA * x);
                float p = __expf(x - ((e < 2) ? Mr0 : Mr1));
                SC[j][e] = p;
                if (e < 2) lsum0 += p; else lsum1 += p;
            }
        }

        // ---- MMA2: O += Ph*Vh + Pl*Vh + Ph*Vl  (V = K tile, ldmatrix.trans) ----
#pragma unroll
        for (int ss = 0; ss < 8; ss++) {
            // Build A-frags from S fragments (bf16 split)
            u32 ah[4], al[4];
#pragma unroll
            for (int q2 = 0; q2 < 4; q2++) {
                const float* src = SC[2 * ss + (q2 >> 1)];
                float v0 = src[(q2 & 1) * 2], v1 = src[(q2 & 1) * 2 + 1];
                u32 hp = packbf(v0, v1);
                float2 f = unpackbf(hp);
                ah[q2] = hp;
                al[q2] = packbf(v0 - f.x, v1 - f.y);
            }
            u32 rowoff = (u32)((16 * ss + rowV_part) * 128);
#pragma unroll
            for (int dp = 0; dp < 4; dp++) {
                u32 ch = (u32)(((2 * dp + (l >> 4)) ^ r7) << 4);
                u32 off = rowoff + ch;
                u32 v0, v1, v2, v3;
                ldsm_x4_t(uKh + off, v0, v1, v2, v3);
                mma16816(OC[2 * dp],     ah, v0, v1);
                mma16816(OC[2 * dp + 1], ah, v2, v3);
                mma16816(OC[2 * dp],     al, v0, v1);
                mma16816(OC[2 * dp + 1], al, v2, v3);
                u32 w0, w1, w2, w3;
                ldsm_x4_t(uKl + off, w0, w1, w2, w3);
                mma16816(OC[2 * dp],     ah, w0, w1);
                mma16816(OC[2 * dp + 1], ah, w2, w3);
            }
        }
    }

    // ---- Reduce row sums across the quad (lanes 4g..4g+3 hold col partials) ----
#pragma unroll
    for (int off = 1; off <= 2; off <<= 1) {
        lsum0 += __shfl_xor_sync(0xffffffffu, lsum0, off);
        lsum1 += __shfl_xor_sync(0xffffffffu, lsum1, off);
    }
    const float inv0 = 1.0f / lsum0;
    const float inv1 = 1.0f / lsum1;

    // ---- Epilogue: normalize, concat heads, add residual ----
    const int b = bh >> 2, hh = bh & 3;
    const int n0 = qb + wrow + g;
    const size_t base0 = ((size_t)(b * NSEQ + n0)) * FIN + hh * DHEAD;
    const size_t base1 = base0 + 8 * FIN;
#pragma unroll
    for (int j = 0; j < 8; j++) {
        int col = 8 * j + 2 * qd;
        float2 h0 = *(const float2*)(hin + base0 + col);
        float2 h1 = *(const float2*)(hin + base1 + col);
        float2 r0, r1;
        r0.x = fmaf(OC[j][0], inv0, h0.x);
        r0.y = fmaf(OC[j][1], inv0, h0.y);
        r1.x = fmaf(OC[j][2], inv1, h1.x);
        r1.y = fmaf(OC[j][3], inv1, h1.y);
        *(float2*)(out + base0 + col) = r0;
        *(float2*)(out + base1 + col) = r1;
    }
}

// ===========================================================================
extern "C" void kernel_launch(void* const* d_in, const int* in_sizes, int n_in,
                              void* d_out, int out_size)
{
    const float* h = (const float*)d_in[0];
    // d_in[1] = adj : unused by the reference computation
    const float* W = (const float*)d_in[2];
    float* out = (float*)d_out;

    proj_kernel<<<dim3(NH, (NB * NSEQ) / 64), 128>>>(h, W);
    norm_kernel<<<BHTOT, 256>>>();

    const int smem_bytes = 65536 + 1024;
    cudaFuncSetAttribute(flash_kernel, cudaFuncAttributeMaxDynamicSharedMemorySize, smem_bytes);
    flash_kernel<<<dim3(NSEQ / QM, BHTOT), 256, smem_bytes>>>(h, out);
}

// round 8
// speedup vs baseline: 2.7735x; 1.0286x over previous
#include <cuda_runtime.h>
#include <cuda_bf16.h>
#include <math.h>
#include <stdint.h>

// Problem constants
#define NB    8
#define NH    4
#define NSEQ  2048
#define FIN   256
#define DHEAD 64
#define ALPHA 0.2f
#define BHTOT (NB*NH)

// Flash tiles
#define QM     128
#define KV     128
#define NTILES (NSEQ/KV)

typedef unsigned long long u64;
typedef unsigned int u32;
typedef unsigned long long ull;

// ===========================================================================
// Helpers
// ===========================================================================
__device__ __forceinline__ u32 smem_u32(const void* p) {
    u32 a;
    asm("{ .reg .u64 t; cvta.to.shared.u64 t, %1; cvt.u32.u64 %0, t; }" : "=r"(a) : "l"(p));
    return a;
}
__device__ __forceinline__ void ldsm_x4(u32 addr, u32& r0, u32& r1, u32& r2, u32& r3) {
    asm volatile("ldmatrix.sync.aligned.m8n8.x4.shared.b16 {%0,%1,%2,%3}, [%4];"
                 : "=r"(r0), "=r"(r1), "=r"(r2), "=r"(r3) : "r"(addr));
}
__device__ __forceinline__ void ldsm_x4_t(u32 addr, u32& r0, u32& r1, u32& r2, u32& r3) {
    asm volatile("ldmatrix.sync.aligned.m8n8.x4.trans.shared.b16 {%0,%1,%2,%3}, [%4];"
                 : "=r"(r0), "=r"(r1), "=r"(r2), "=r"(r3) : "r"(addr));
}
__device__ __forceinline__ void mma16816(float* c, const u32* a, u32 b0, u32 b1) {
    asm volatile("mma.sync.aligned.m16n8k16.row.col.f32.bf16.bf16.f32 "
                 "{%0,%1,%2,%3}, {%4,%5,%6,%7}, {%8,%9}, {%0,%1,%2,%3};"
                 : "+f"(c[0]), "+f"(c[1]), "+f"(c[2]), "+f"(c[3])
                 : "r"(a[0]), "r"(a[1]), "r"(a[2]), "r"(a[3]), "r"(b0), "r"(b1));
}
__device__ __forceinline__ u32 packbf(float lo, float hi) {
    __nv_bfloat162 t = __floats2bfloat162_rn(lo, hi);   // .x = lo (low half)
    return *(u32*)&t;
}
__device__ __forceinline__ float2 unpackbf(u32 v) {
    return __bfloat1622float2(*(__nv_bfloat162*)&v);
}

// f32x2 packed FMA helpers (projection kernel)
__device__ __forceinline__ ull bc2(float x) {
    ull r; asm("mov.b64 %0, {%1, %1};" : "=l"(r) : "r"(__float_as_uint(x))); return r;
}
__device__ __forceinline__ void up2(ull v, float& lo, float& hi) {
    u32 a, b; asm("mov.b64 {%0, %1}, %2;" : "=r"(a), "=r"(b) : "l"(v));
    lo = __uint_as_float(a); hi = __uint_as_float(b);
}
__device__ __forceinline__ void fma2(ull& d, ull a, ull b) {
    asm("fma.rn.f32x2 %0, %1, %2, %0;" : "+l"(d) : "l"(a), "l"(b));
}

// ===========================================================================
// Global scratch (no allocs allowed)
// ===========================================================================
__device__ __nv_bfloat16 g_Ph[(size_t)BHTOT * NSEQ * DHEAD];
__device__ __nv_bfloat16 g_Pl[(size_t)BHTOT * NSEQ * DHEAD];
__device__ float g_norm2[(size_t)BHTOT * NSEQ];
__device__ float g_kmax2[BHTOT];

// ===========================================================================
// Kernel 1: projection P = h @ W  -> bf16 split (hi, lo)
// ===========================================================================
__global__ __launch_bounds__(128) void proj_kernel(const float* __restrict__ hin,
                                                   const float* __restrict__ W)
{
    __shared__ float Ast[16][68];
    __shared__ float Bs [16][68];

    const int tid = threadIdx.x;
    const int ct  = blockIdx.x;
    const int rt  = blockIdx.y;
    const int tx  = tid & 15;
    const int ty  = tid >> 4;

    const float* Atile = hin + (size_t)rt * 64 * FIN;
    const float* Btile = W   + (size_t)ct * FIN * DHEAD;

    ull acc2[4][4];
#pragma unroll
    for (int i = 0; i < 4; i++)
#pragma unroll
        for (int j = 0; j < 4; j++) acc2[i][j] = 0ULL;

    for (int k0 = 0; k0 < FIN; k0 += 16) {
#pragma unroll
        for (int i = 0; i < 2; i++) {
            int f4 = i * 128 + tid;
            int row = f4 >> 2, kk = (f4 & 3) * 4;
            float4 v = *(const float4*)(Atile + (size_t)row * FIN + k0 + kk);
            Ast[kk + 0][row] = v.x; Ast[kk + 1][row] = v.y;
            Ast[kk + 2][row] = v.z; Ast[kk + 3][row] = v.w;
        }
#pragma unroll
        for (int i = 0; i < 2; i++) {
            int f4 = i * 128 + tid;
            int kk = f4 >> 4, dd = (f4 & 15) * 4;
            *(float4*)&Bs[kk][dd] = *(const float4*)(Btile + (size_t)(k0 + kk) * DHEAD + dd);
        }
        __syncthreads();
#pragma unroll
        for (int k = 0; k < 16; k++) {
            ulonglong2 a0 = *(ulonglong2*)&Ast[k][ty * 8];
            ulonglong2 a1 = *(ulonglong2*)&Ast[k][ty * 8 + 4];
            float4 bv = *(float4*)&Bs[k][tx * 4];
            ull ap[4] = {a0.x, a0.y, a1.x, a1.y};
            ull b0 = bc2(bv.x), b1 = bc2(bv.y), b2 = bc2(bv.z), b3 = bc2(bv.w);
#pragma unroll
            for (int i = 0; i < 4; i++) {
                fma2(acc2[i][0], ap[i], b0); fma2(acc2[i][1], ap[i], b1);
                fma2(acc2[i][2], ap[i], b2); fma2(acc2[i][3], ap[i], b3);
            }
        }
        __syncthreads();
    }

#pragma unroll
    for (int i2 = 0; i2 < 4; i2++) {
        float lo[4], hi[4];
#pragma unroll
        for (int j = 0; j < 4; j++) up2(acc2[i2][j], lo[j], hi[j]);
#pragma unroll
        for (int p = 0; p < 2; p++) {
            int grow = rt * 64 + ty * 8 + i2 * 2 + p;
            int b = grow >> 11, n = grow & 2047;
            size_t off = (((size_t)(b * NH + ct) * NSEQ + n) * DHEAD) + tx * 4;
            const float* src = p ? hi : lo;
#pragma unroll
            for (int j = 0; j < 4; j++) {
                float v = src[j];
                __nv_bfloat16 vh = __float2bfloat16(v);
                float vl = v - __bfloat162float(vh);
                g_Ph[off + j] = vh;
                g_Pl[off + j] = __float2bfloat16(vl);
            }
        }
    }
}

// ===========================================================================
// Kernel 2: row norms + per-(b,h) max norm^2
// ===========================================================================
__global__ __launch_bounds__(256) void norm_kernel()
{
    const int bh = blockIdx.x;
    const int tid = threadIdx.x;
    float mx = 0.f;
    for (int r = tid; r < NSEQ; r += 256) {
        const uint4* ph = (const uint4*)(g_Ph + ((size_t)bh * NSEQ + r) * DHEAD);
        const uint4* pl = (const uint4*)(g_Pl + ((size_t)bh * NSEQ + r) * DHEAD);
        float s = 0.f;
#pragma unroll
        for (int g = 0; g < 8; g++) {
            uint4 a = ph[g], b = pl[g];
            const u32 wa[4] = {a.x, a.y, a.z, a.w};
            const u32 wb[4] = {b.x, b.y, b.z, b.w};
#pragma unroll
            for (int q = 0; q < 4; q++) {
                float2 fa = unpackbf(wa[q]);
                float2 fb = unpackbf(wb[q]);
                float v0 = fa.x + fb.x, v1 = fa.y + fb.y;
                s = fmaf(v0, v0, s); s = fmaf(v1, v1, s);
            }
        }
        g_norm2[(size_t)bh * NSEQ + r] = s;
        mx = fmaxf(mx, s);
    }
    __shared__ float red[8];
#pragma unroll
    for (int off = 16; off >= 1; off >>= 1)
        mx = fmaxf(mx, __shfl_xor_sync(0xffffffffu, mx, off));
    if ((tid & 31) == 0) red[tid >> 5] = mx;
    __syncthreads();
    if (tid == 0) {
        float m = red[0];
#pragma unroll
        for (int w = 1; w < 8; w++) m = fmaxf(m, red[w]);
        g_kmax2[bh] = m;
    }
}

// ===========================================================================
// Kernel 3: mma.sync flash attention (no-rescale single pass) + residual
// 8 warps; warp w owns Q rows [w*16, w*16+16). smem: Qh|Ql|Kh|Kl 16KB each.
// KV tile processed in two 64-col halves (SC regs halved -> occ 2).
// MMA2 full 3-term bf16: Ph*Vh + Pl*Vh + Ph*Vl (R6-proven accuracy).
// ===========================================================================
extern __shared__ char dyn_smem[];

__global__ __launch_bounds__(256, 2) void flash_kernel(const float* __restrict__ hin,
                                                       float* __restrict__ out)
{
    const int tid = threadIdx.x;
    const int l   = tid & 31;
    const int wid = tid >> 5;
    const int wrow = wid * 16;
    const int g   = l >> 2;        // 0..7
    const int qd  = l & 3;
    const int r7  = l & 7;
    const int bh  = blockIdx.y;
    const int qb  = blockIdx.x * QM;

    // Align smem base to 1KB so swizzle math is clean
    const u32 s_raw = smem_u32(dyn_smem);
    const u32 s0 = (s_raw + 1023u) & ~1023u;
    char* base = dyn_smem + (s0 - s_raw);
    char* Qh = base;          char* Ql = base + 16384;
    char* Kh = base + 32768;  char* Kl = base + 49152;
    const u32 uQh = s0, uQl = s0 + 16384, uKh = s0 + 32768, uKl = s0 + 49152;

    const uint4* gPh = (const uint4*)(g_Ph + (size_t)bh * NSEQ * DHEAD);
    const uint4* gPl = (const uint4*)(g_Pl + (size_t)bh * NSEQ * DHEAD);

    // ---- Load Q tile (hi/lo) with swizzle: 128 rows x 128B ----
#pragma unroll
    for (int i = 0; i < 4; i++) {
        int idx = i * 256 + tid;
        int row = idx >> 3, ch = idx & 7;
        u32 dst = (u32)(row * 128 + ((ch ^ (row & 7)) << 4));
        *(uint4*)(Qh + dst) = gPh[(qb + row) * 8 + ch];
        *(uint4*)(Ql + dst) = gPl[(qb + row) * 8 + ch];
    }
    __syncthreads();

    // ---- Load Q A-fragments (resident all tiles): 4 k-steps x 4 regs x 2 ----
    u32 Ah[4][4], Al[4][4];
#pragma unroll
    for (int s = 0; s < 4; s++) {
        u32 row = (u32)(wrow + (l & 15));
        u32 ch  = (u32)((2 * s + (l >> 4)) ^ r7);
        u32 off = row * 128 + (ch << 4);
        ldsm_x4(uQh + off, Ah[s][0], Ah[s][1], Ah[s][2], Ah[s][3]);
        ldsm_x4(uQl + off, Al[s][0], Al[s][1], Al[s][2], Al[s][3]);
    }

    // ---- Per-row softmax shift: M_r = sqrt(|q_r|^2 * max_k |k|^2) ----
    const float km2 = g_kmax2[bh];
    const float Mr0 = sqrtf(g_norm2[(size_t)bh * NSEQ + qb + wrow + g] * km2);
    const float Mr1 = sqrtf(g_norm2[(size_t)bh * NSEQ + qb + wrow + g + 8] * km2);

    float OC[8][4];
#pragma unroll
    for (int j = 0; j < 8; j++)
#pragma unroll
        for (int e = 0; e < 4; e++) OC[j][e] = 0.f;
    float lsum0 = 0.f, lsum1 = 0.f;

    // Precomputed addressing pieces
    const u32 rowB_off = (u32)((8 * (l >> 4) + r7) * 128);   // MMA1 B row part
    const u32 cbB = (u32)((l >> 3) & 1);                     // MMA1 B chunk half
    const u32 rowV_part = (u32)(l & 15);                     // MMA2 V row part

    for (int t = 0; t < NTILES; t++) {
        __syncthreads();   // previous iteration's ldmatrix reads complete

        // ---- Load K tile t (hi/lo) ----
#pragma unroll
        for (int i = 0; i < 4; i++) {
            int idx = i * 256 + tid;
            int row = idx >> 3, ch = idx & 7;
            u32 dst = (u32)(row * 128 + ((ch ^ (row & 7)) << 4));
            *(uint4*)(Kh + dst) = gPh[(t * KV + row) * 8 + ch];
            *(uint4*)(Kl + dst) = gPl[(t * KV + row) * 8 + ch];
        }
        __syncthreads();

        // ---- Process tile in two 64-column halves ----
#pragma unroll
        for (int hf = 0; hf < 2; hf++) {
            // MMA1: S = Qh*Kh^T + Ql*Kh^T + Qh*Kl^T  (64 cols of this half)
            float SC[8][4];
#pragma unroll
            for (int j = 0; j < 8; j++)
#pragma unroll
                for (int e = 0; e < 4; e++) SC[j][e] = 0.f;

#pragma unroll
            for (int s = 0; s < 4; s++) {
                u32 chsw = (u32)(((2 * s + cbB) ^ r7) << 4);
#pragma unroll
                for (int jp = 0; jp < 4; jp++) {
                    u32 off = (u32)((hf * 4 + jp) * 16 * 128) + rowB_off + chsw;
                    u32 b0, b1, b2, b3;
                    ldsm_x4(uKh + off, b0, b1, b2, b3);
                    mma16816(SC[2 * jp],     Ah[s], b0, b1);
                    mma16816(SC[2 * jp + 1], Ah[s], b2, b3);
                    mma16816(SC[2 * jp],     Al[s], b0, b1);
                    mma16816(SC[2 * jp + 1], Al[s], b2, b3);
                    u32 c0, c1, c2, c3;
                    ldsm_x4(uKl + off, c0, c1, c2, c3);
                    mma16816(SC[2 * jp],     Ah[s], c0, c1);
                    mma16816(SC[2 * jp + 1], Ah[s], c2, c3);
                }
            }

            // LeakyReLU + exp(x - Mr), accumulate row sums
#pragma unroll
            for (int j = 0; j < 8; j++) {
#pragma unroll
                for (int e = 0; e < 4; e++) {
                    float x = SC[j][e];
                    x = fmaxf(x, ALPHA * x);
                    float p = __expf(x - ((e < 2) ? Mr0 : Mr1));
                    SC[j][e] = p;
                    if (e < 2) lsum0 += p; else lsum1 += p;
                }
            }

            // Build bf16 A-frags for MMA2: hi + lo split of P
            u32 pah[4][4], pal[4][4];
#pragma unroll
            for (int ss = 0; ss < 4; ss++) {
#pragma unroll
                for (int q2 = 0; q2 < 4; q2++) {
                    const float* src = SC[2 * ss + (q2 >> 1)];
                    float v0 = src[(q2 & 1) * 2], v1 = src[(q2 & 1) * 2 + 1];
                    u32 hp = packbf(v0, v1);
                    float2 f = unpackbf(hp);
                    pah[ss][q2] = hp;
                    pal[ss][q2] = packbf(v0 - f.x, v1 - f.y);
                }
            }

            // MMA2: O += Ph*Vh + Pl*Vh + Ph*Vl  (V = K tile, ldmatrix.trans)
#pragma unroll
            for (int ss = 0; ss < 4; ss++) {
                u32 rowoff = (u32)((hf * 64 + 16 * ss + rowV_part) * 128);
#pragma unroll
                for (int dp = 0; dp < 4; dp++) {
                    u32 ch = (u32)(((2 * dp + (l >> 4)) ^ r7) << 4);
                    u32 v0, v1, v2, v3;
                    ldsm_x4_t(uKh + rowoff + ch, v0, v1, v2, v3);
                    mma16816(OC[2 * dp],     pah[ss], v0, v1);
                    mma16816(OC[2 * dp + 1], pah[ss], v2, v3);
                    mma16816(OC[2 * dp],     pal[ss], v0, v1);
                    mma16816(OC[2 * dp + 1], pal[ss], v2, v3);
                    u32 w0, w1, w2, w3;
                    ldsm_x4_t(uKl + rowoff + ch, w0, w1, w2, w3);
                    mma16816(OC[2 * dp],     pah[ss], w0, w1);
                    mma16816(OC[2 * dp + 1], pah[ss], w2, w3);
                }
            }
        }
    }

    // ---- Reduce row sums across the quad ----
#pragma unroll
    for (int off = 1; off <= 2; off <<= 1) {
        lsum0 += __shfl_xor_sync(0xffffffffu, lsum0, off);
        lsum1 += __shfl_xor_sync(0xffffffffu, lsum1, off);
    }
    const float inv0 = 1.0f / lsum0;
    const float inv1 = 1.0f / lsum1;

    // ---- Epilogue: normalize, concat heads, add residual ----
    const int b = bh >> 2, hh = bh & 3;
    const int n0 = qb + wrow + g;
    const size_t base0 = ((size_t)(b * NSEQ + n0)) * FIN + hh * DHEAD;
    const size_t base1 = base0 + 8 * FIN;
#pragma unroll
    for (int j = 0; j < 8; j++) {
        int col = 8 * j + 2 * qd;
        float2 h0 = *(const float2*)(hin + base0 + col);
        float2 h1 = *(const float2*)(hin + base1 + col);
        float2 r0, r1;
        r0.x = fmaf(OC[j][0], inv0, h0.x);
        r0.y = fmaf(OC[j][1], inv0, h0.y);
        r1.x = fmaf(OC[j][2], inv1, h1.x);
        r1.y = fmaf(OC[j][3], inv1, h1.y);
        *(float2*)(out + base0 + col) = r0;
        *(float2*)(out + base1 + col) = r1;
    }
}

// ===========================================================================
extern "C" void kernel_launch(void* const* d_in, const int* in_sizes, int n_in,
                              void* d_out, int out_size)
{
    const float* h = (const float*)d_in[0];
    // d_in[1] = adj : unused by the reference computation
    const float* W = (const float*)d_in[2];
    float* out = (float*)d_out;

    proj_kernel<<<dim3(NH, (NB * NSEQ) / 64), 128>>>(h, W);
    norm_kernel<<<BHTOT, 256>>>();

    const int smem_bytes = 65536 + 1024;
    cudaFuncSetAttribute(flash_kernel, cudaFuncAttributeMaxDynamicSharedMemorySize, smem_bytes);
    flash_kernel<<<dim3(NSEQ / QM, BHTOT), 256, smem_bytes>>>(h, out);
}

// round 11
// speedup vs baseline: 2.9569x; 1.0661x over previous
#include <cuda_runtime.h>
#include <cuda_bf16.h>
#include <math.h>
#include <stdint.h>

// Problem constants
#define NB    8
#define NH    4
#define NSEQ  2048
#define FIN   256
#define DHEAD 64
#define ALPHA 0.2f
#define BHTOT (NB*NH)

// Flash tiles
#define QM     128
#define KV     128
#define NTILES (NSEQ/KV)

typedef unsigned long long u64;
typedef unsigned int u32;

// ===========================================================================
// Helpers
// ===========================================================================
__device__ __forceinline__ u32 smem_u32(const void* p) {
    u32 a;
    asm("{ .reg .u64 t; cvta.to.shared.u64 t, %1; cvt.u32.u64 %0, t; }" : "=r"(a) : "l"(p));
    return a;
}
__device__ __forceinline__ void ldsm_x4(u32 addr, u32& r0, u32& r1, u32& r2, u32& r3) {
    asm volatile("ldmatrix.sync.aligned.m8n8.x4.shared.b16 {%0,%1,%2,%3}, [%4];"
                 : "=r"(r0), "=r"(r1), "=r"(r2), "=r"(r3) : "r"(addr));
}
__device__ __forceinline__ void ldsm_x4_t(u32 addr, u32& r0, u32& r1, u32& r2, u32& r3) {
    asm volatile("ldmatrix.sync.aligned.m8n8.x4.trans.shared.b16 {%0,%1,%2,%3}, [%4];"
                 : "=r"(r0), "=r"(r1), "=r"(r2), "=r"(r3) : "r"(addr));
}
__device__ __forceinline__ void mma16816(float* c, const u32* a, u32 b0, u32 b1) {
    asm volatile("mma.sync.aligned.m16n8k16.row.col.f32.bf16.bf16.f32 "
                 "{%0,%1,%2,%3}, {%4,%5,%6,%7}, {%8,%9}, {%0,%1,%2,%3};"
                 : "+f"(c[0]), "+f"(c[1]), "+f"(c[2]), "+f"(c[3])
                 : "r"(a[0]), "r"(a[1]), "r"(a[2]), "r"(a[3]), "r"(b0), "r"(b1));
}
__device__ __forceinline__ u32 packbf(float lo, float hi) {
    __nv_bfloat162 t = __floats2bfloat162_rn(lo, hi);   // .x = lo (low half)
    return *(u32*)&t;
}
__device__ __forceinline__ float2 unpackbf(u32 v) {
    return __bfloat1622float2(*(__nv_bfloat162*)&v);
}

// ===========================================================================
// Global scratch (no allocs allowed)
// ===========================================================================
__device__ __nv_bfloat16 g_Ph[(size_t)BHTOT * NSEQ * DHEAD];
__device__ __nv_bfloat16 g_Pl[(size_t)BHTOT * NSEQ * DHEAD];
__device__ float g_norm2[(size_t)BHTOT * NSEQ];
__device__ int   g_kmax2i[BHTOT];   // fp32 bits, positive -> int atomicMax works

// ===========================================================================
// Kernel 1: tensor-core projection  P = h @ W[head]  (3-term split bf16)
//   + fused row-norm (for softmax shift) + per-(b,h) max via atomicMax.
// CTA: 128 rows x 64 cols (one head). 8 warps, warp = 16 rows.
// K chunked by 64. smem: Ash/Asl 16KB each, Wsh/Wsl 8KB each = 48KB.
// ===========================================================================
extern __shared__ char proj_smem[];

__global__ __launch_bounds__(256, 2) void proj_tc_kernel(const float* __restrict__ hin,
                                                         const float* __restrict__ W)
{
    const int tid = threadIdx.x;
    const int l   = tid & 31;
    const int wid = tid >> 5;
    const int wrow = wid * 16;
    const int g   = l >> 2;
    const int qd  = l & 3;
    const int r7  = l & 7;
    const int ct  = blockIdx.x;       // head
    const int rt  = blockIdx.y;       // 128-row tile over 16384 rows

    const u32 s_raw = smem_u32(proj_smem);
    const u32 s0 = (s_raw + 1023u) & ~1023u;
    char* base = proj_smem + (s0 - s_raw);
    char* Ash = base;            char* Asl = base + 16384;
    char* Wsh = base + 32768;    char* Wsl = base + 40960;
    const u32 uAh = s0, uAl = s0 + 16384, uWh = s0 + 32768, uWl = s0 + 40960;

    float OC[8][4];
#pragma unroll
    for (int j = 0; j < 8; j++)
#pragma unroll
        for (int e = 0; e < 4; e++) OC[j][e] = 0.f;

    const u32 rowB_off = (u32)((8 * (l >> 4) + r7) * 128);
    const u32 cbB = (u32)((l >> 3) & 1);
    const u32 qrow_off = (u32)((wrow + (l & 15)) * 128);

    for (int kc = 0; kc < 4; kc++) {
        __syncthreads();   // protect smem reuse from previous chunk's ldmatrix

        // ---- Load A chunk: 128 rows x 64 f (fp32) -> hi/lo bf16, swizzled ----
#pragma unroll
        for (int i = 0; i < 16; i++) {
            int e = i * 256 + tid;            // 0..4095 (pairs)
            int row = e >> 5, fp = e & 31;    // fp = pair index (2 floats)
            float2 v = *(const float2*)(hin + (size_t)(rt * 128 + row) * FIN + kc * 64 + fp * 2);
            u32 hp = packbf(v.x, v.y);
            float2 f = unpackbf(hp);
            u32 lp = packbf(v.x - f.x, v.y - f.y);
            u32 addr = (u32)(row * 128 + ((((fp >> 2) ^ (row & 7)) << 4) + (fp & 3) * 4));
            *(u32*)(Ash + addr) = hp;
            *(u32*)(Asl + addr) = lp;
        }
        // ---- Load W chunk transposed: [d=64][f=64] hi/lo, swizzled ----
#pragma unroll
        for (int i = 0; i < 16; i++) {
            int e = i * 256 + tid;            // 0..4095
            int f = e >> 6, d = e & 63;
            float v = W[(size_t)ct * FIN * DHEAD + (size_t)(kc * 64 + f) * DHEAD + d];
            __nv_bfloat16 vh = __float2bfloat16(v);
            float vl = v - __bfloat162float(vh);
            u32 addr = (u32)(d * 128 + (((f >> 3) ^ (d & 7)) << 4) + (f & 7) * 2);
            *(__nv_bfloat16*)(Wsh + addr) = vh;
            *(__nv_bfloat16*)(Wsl + addr) = __float2bfloat16(vl);
        }
        __syncthreads();

        // ---- MMA: OC += Ah*Wh + Al*Wh + Ah*Wl ----
#pragma unroll
        for (int s = 0; s < 4; s++) {
            u32 qh[4], ql[4];
            u32 offq = qrow_off + (u32)(((2 * s + (l >> 4)) ^ r7) << 4);
            ldsm_x4(uAh + offq, qh[0], qh[1], qh[2], qh[3]);
            ldsm_x4(uAl + offq, ql[0], ql[1], ql[2], ql[3]);
            u32 chsw = (u32)(((2 * s + cbB) ^ r7) << 4);
#pragma unroll
            for (int jp = 0; jp < 4; jp++) {
                u32 off = (u32)(jp * 16 * 128) + rowB_off + chsw;
                u32 b0, b1, b2, b3;
                ldsm_x4(uWh + off, b0, b1, b2, b3);
                mma16816(OC[2 * jp],     qh, b0, b1);
                mma16816(OC[2 * jp + 1], qh, b2, b3);
                mma16816(OC[2 * jp],     ql, b0, b1);
                mma16816(OC[2 * jp + 1], ql, b2, b3);
                u32 c0, c1, c2, c3;
                ldsm_x4(uWl + off, c0, c1, c2, c3);
                mma16816(OC[2 * jp],     qh, c0, c1);
                mma16816(OC[2 * jp + 1], qh, c2, c3);
            }
        }
    }

    // ---- Epilogue: row norms + split-bf16 store of P ----
    float nrm0 = 0.f, nrm1 = 0.f;
#pragma unroll
    for (int j = 0; j < 8; j++) {
        nrm0 = fmaf(OC[j][0], OC[j][0], nrm0);
        nrm0 = fmaf(OC[j][1], OC[j][1], nrm0);
        nrm1 = fmaf(OC[j][2], OC[j][2], nrm1);
        nrm1 = fmaf(OC[j][3], OC[j][3], nrm1);
    }
#pragma unroll
    for (int off = 1; off <= 2; off <<= 1) {
        nrm0 += __shfl_xor_sync(0xffffffffu, nrm0, off);
        nrm1 += __shfl_xor_sync(0xffffffffu, nrm1, off);
    }

    const int grow0 = rt * 128 + wrow + g;     // global row (b*N + n)
    const int b0 = grow0 >> 11, n0 = grow0 & 2047;
    const int bh = b0 * NH + ct;
    const size_t prow0 = (size_t)bh * NSEQ + n0;
    const size_t prow1 = prow0 + 8;

    if (qd == 0) {
        g_norm2[prow0] = nrm0;
        g_norm2[prow1] = nrm1;
        atomicMax(&g_kmax2i[bh], __float_as_int(fmaxf(nrm0, nrm1)));
    }

    u32* ph32 = (u32*)g_Ph;
    u32* pl32 = (u32*)g_Pl;
#pragma unroll
    for (int j = 0; j < 8; j++) {
        // rows prow0/prow1, cols d = 8j + 2qd, 8j + 2qd + 1
        u32 h0 = packbf(OC[j][0], OC[j][1]);
        float2 f0 = unpackbf(h0);
        u32 l0 = packbf(OC[j][0] - f0.x, OC[j][1] - f0.y);
        u32 h1 = packbf(OC[j][2], OC[j][3]);
        float2 f1 = unpackbf(h1);
        u32 l1 = packbf(OC[j][2] - f1.x, OC[j][3] - f1.y);
        size_t i0 = prow0 * 32 + 4 * j + qd;
        size_t i1 = prow1 * 32 + 4 * j + qd;
        ph32[i0] = h0; pl32[i0] = l0;
        ph32[i1] = h1; pl32[i1] = l1;
    }
}

// ===========================================================================
// Kernel 2: mma.sync flash attention (no-rescale single pass) + residual
// 8 warps; warp w owns Q rows [w*16, w*16+16). smem: Qh|Ql|Kh|Kl 16KB each.
// KV tile in two 64-col halves; Q frags reloaded per k-step; P pack
// interleaved with MMA2 per ss-group  => regs fit 128 => occ 2 (real).
// MMA2 full 3-term bf16: Ph*Vh + Pl*Vh + Ph*Vl.
// ===========================================================================
extern __shared__ char dyn_smem[];

__global__ __launch_bounds__(256, 2) void flash_kernel(const float* __restrict__ hin,
                                                       float* __restrict__ out)
{
    const int tid = threadIdx.x;
    const int l   = tid & 31;
    const int wid = tid >> 5;
    const int wrow = wid * 16;
    const int g   = l >> 2;        // 0..7
    const int qd  = l & 3;
    const int r7  = l & 7;
    const int bh  = blockIdx.y;
    const int qb  = blockIdx.x * QM;

    const u32 s_raw = smem_u32(dyn_smem);
    const u32 s0 = (s_raw + 1023u) & ~1023u;
    char* base = dyn_smem + (s0 - s_raw);
    char* Qh = base;          char* Ql = base + 16384;
    char* Kh = base + 32768;  char* Kl = base + 49152;
    const u32 uQh = s0, uQl = s0 + 16384, uKh = s0 + 32768, uKl = s0 + 49152;

    const uint4* gPh = (const uint4*)(g_Ph + (size_t)bh * NSEQ * DHEAD);
    const uint4* gPl = (const uint4*)(g_Pl + (size_t)bh * NSEQ * DHEAD);

    // ---- Load Q tile (hi/lo) with swizzle: 128 rows x 128B ----
#pragma unroll
    for (int i = 0; i < 4; i++) {
        int idx = i * 256 + tid;
        int row = idx >> 3, ch = idx & 7;
        u32 dst = (u32)(row * 128 + ((ch ^ (row & 7)) << 4));
        *(uint4*)(Qh + dst) = gPh[(qb + row) * 8 + ch];
        *(uint4*)(Ql + dst) = gPl[(qb + row) * 8 + ch];
    }

    // ---- Per-row softmax shift: M_r = sqrt(|q_r|^2 * max_k |k|^2) ----
    const float km2 = __int_as_float(g_kmax2i[bh]);
    const float Mr0 = sqrtf(g_norm2[(size_t)bh * NSEQ + qb + wrow + g] * km2);
    const float Mr1 = sqrtf(g_norm2[(size_t)bh * NSEQ + qb + wrow + g + 8] * km2);

    float OC[8][4];
#pragma unroll
    for (int j = 0; j < 8; j++)
#pragma unroll
        for (int e = 0; e < 4; e++) OC[j][e] = 0.f;
    float lsum0 = 0.f, lsum1 = 0.f;

    // Precomputed addressing pieces
    const u32 rowB_off = (u32)((8 * (l >> 4) + r7) * 128);   // MMA1 B row part
    const u32 cbB = (u32)((l >> 3) & 1);                     // MMA1 B chunk half
    const u32 rowV_part = (u32)(l & 15);                     // MMA2 V row part
    const u32 qrow_off = (u32)((wrow + (l & 15)) * 128);     // Q frag row part

    for (int t = 0; t < NTILES; t++) {
        __syncthreads();   // previous iteration's ldmatrix reads complete

        // ---- Load K tile t (hi/lo) ----
#pragma unroll
        for (int i = 0; i < 4; i++) {
            int idx = i * 256 + tid;
            int row = idx >> 3, ch = idx & 7;
            u32 dst = (u32)(row * 128 + ((ch ^ (row & 7)) << 4));
            *(uint4*)(Kh + dst) = gPh[(t * KV + row) * 8 + ch];
            *(uint4*)(Kl + dst) = gPl[(t * KV + row) * 8 + ch];
        }
        __syncthreads();

        // ---- Process tile in two 64-column halves ----
#pragma unroll
        for (int hf = 0; hf < 2; hf++) {
            // MMA1: S = Qh*Kh^T + Ql*Kh^T + Qh*Kl^T  (64 cols of this half)
            float SC[8][4];
#pragma unroll
            for (int j = 0; j < 8; j++)
#pragma unroll
                for (int e = 0; e < 4; e++) SC[j][e] = 0.f;

#pragma unroll
            for (int s = 0; s < 4; s++) {
                u32 qh[4], ql[4];
                u32 offq = qrow_off + (u32)(((2 * s + (l >> 4)) ^ r7) << 4);
                ldsm_x4(uQh + offq, qh[0], qh[1], qh[2], qh[3]);
                ldsm_x4(uQl + offq, ql[0], ql[1], ql[2], ql[3]);
                u32 chsw = (u32)(((2 * s + cbB) ^ r7) << 4);
#pragma unroll
                for (int jp = 0; jp < 4; jp++) {
                    u32 off = (u32)((hf * 4 + jp) * 16 * 128) + rowB_off + chsw;
                    u32 b0, b1, b2, b3;
                    ldsm_x4(uKh + off, b0, b1, b2, b3);
                    mma16816(SC[2 * jp],     qh, b0, b1);
                    mma16816(SC[2 * jp + 1], qh, b2, b3);
                    mma16816(SC[2 * jp],     ql, b0, b1);
                    mma16816(SC[2 * jp + 1], ql, b2, b3);
                    u32 c0, c1, c2, c3;
                    ldsm_x4(uKl + off, c0, c1, c2, c3);
                    mma16816(SC[2 * jp],     qh, c0, c1);
                    mma16816(SC[2 * jp + 1], qh, c2, c3);
                }
            }

            // LeakyReLU + exp(x - Mr), accumulate row sums
#pragma unroll
            for (int j = 0; j < 8; j++) {
#pragma unroll
                for (int e = 0; e < 4; e++) {
                    float x = SC[j][e];
                    x = fmaxf(x, ALPHA * x);
                    float p = __expf(x - ((e < 2) ? Mr0 : Mr1));
                    SC[j][e] = p;
                    if (e < 2) lsum0 += p; else lsum1 += p;
                }
            }

            // MMA2 per ss-group: pack P frags (hi/lo) then multiply into O
#pragma unroll
            for (int ss = 0; ss < 4; ss++) {
                u32 pah[4], pal[4];
#pragma unroll
                for (int q2 = 0; q2 < 4; q2++) {
                    const float* src = SC[2 * ss + (q2 >> 1)];
                    float v0 = src[(q2 & 1) * 2], v1 = src[(q2 & 1) * 2 + 1];
                    u32 hp = packbf(v0, v1);
                    float2 f = unpackbf(hp);
                    pah[q2] = hp;
                    pal[q2] = packbf(v0 - f.x, v1 - f.y);
                }
                u32 rowoff = (u32)((hf * 64 + 16 * ss + rowV_part) * 128);
#pragma unroll
                for (int dp = 0; dp < 4; dp++) {
                    u32 ch = (u32)(((2 * dp + (l >> 4)) ^ r7) << 4);
                    u32 v0, v1, v2, v3;
                    ldsm_x4_t(uKh + rowoff + ch, v0, v1, v2, v3);
                    mma16816(OC[2 * dp],     pah, v0, v1);
                    mma16816(OC[2 * dp + 1], pah, v2, v3);
                    mma16816(OC[2 * dp],     pal, v0, v1);
                    mma16816(OC[2 * dp + 1], pal, v2, v3);
                    u32 w0, w1, w2, w3;
                    ldsm_x4_t(uKl + rowoff + ch, w0, w1, w2, w3);
                    mma16816(OC[2 * dp],     pah, w0, w1);
                    mma16816(OC[2 * dp + 1], pah, w2, w3);
                }
            }
        }
    }

    // ---- Reduce row sums across the quad ----
#pragma unroll
    for (int off = 1; off <= 2; off <<= 1) {
        lsum0 += __shfl_xor_sync(0xffffffffu, lsum0, off);
        lsum1 += __shfl_xor_sync(0xffffffffu, lsum1, off);
    }
    const float inv0 = 1.0f / lsum0;
    const float inv1 = 1.0f / lsum1;

    // ---- Epilogue: normalize, concat heads, add residual ----
    const int b = bh >> 2, hh = bh & 3;
    const int n0 = qb + wrow + g;
    const size_t base0 = ((size_t)(b * NSEQ + n0)) * FIN + hh * DHEAD;
    const size_t base1 = base0 + 8 * FIN;
#pragma unroll
    for (int j = 0; j < 8; j++) {
        int col = 8 * j + 2 * qd;
        float2 h0 = *(const float2*)(hin + base0 + col);
        float2 h1 = *(const float2*)(hin + base1 + col);
        float2 r0, r1;
        r0.x = fmaf(OC[j][0], inv0, h0.x);
        r0.y = fmaf(OC[j][1], inv0, h0.y);
        r1.x = fmaf(OC[j][2], inv1, h1.x);
        r1.y = fmaf(OC[j][3], inv1, h1.y);
        *(float2*)(out + base0 + col) = r0;
        *(float2*)(out + base1 + col) = r1;
    }
}

// ===========================================================================
extern "C" void kernel_launch(void* const* d_in, const int* in_sizes, int n_in,
                              void* d_out, int out_size)
{
    const float* h = (const float*)d_in[0];
    // d_in[1] = adj : unused by the reference computation
    const float* W = (const float*)d_in[2];
    float* out = (float*)d_out;

    const int proj_smem_bytes = 49152 + 1024;
    cudaFuncSetAttribute(proj_tc_kernel, cudaFuncAttributeMaxDynamicSharedMemorySize,
                         proj_smem_bytes);
    proj_tc_kernel<<<dim3(NH, (NB * NSEQ) / 128), 256, proj_smem_bytes>>>(h, W);

    const int smem_bytes = 65536 + 1024;
    cudaFuncSetAttribute(flash_kernel, cudaFuncAttributeMaxDynamicSharedMemorySize, smem_bytes);
    flash_kernel<<<dim3(NSEQ / QM, BHTOT), 256, smem_bytes>>>(h, out);
}